// round 2
// baseline (speedup 1.0000x reference)
#include <cuda_runtime.h>
#include <cuda_bf16.h>
#include <mma.h>
#include <math.h>

using namespace nvcuda;

// ---------------- problem constants ----------------
constexpr int B_   = 4;
constexpr int S_   = 4096;
constexpr int D_   = 1024;   // token dim
constexpr int H_   = 1024;   // hidden dim
constexpr int WIN  = 256;
constexpr int STRIDE_ = 128;
constexpr int GLOB = 16;
constexpr float EPS = 1e-5f;
constexpr float SCALE = 1.0f / 32.0f;  // 1/sqrt(1024)

constexpr int ROWS = B_ * S_;          // 16384
constexpr size_t NELEM = (size_t)ROWS * D_;  // 16,777,216

// ---------------- scratch (static device globals; allocation-free) ----------
__device__ __nv_bfloat16 g_x[NELEM];       // LN1 output (bf16)
__device__ __nv_bfloat16 g_wq[D_ * H_];
__device__ __nv_bfloat16 g_wk[D_ * H_];
__device__ __nv_bfloat16 g_wv[D_ * D_];
__device__ __nv_bfloat16 g_wo[D_ * D_];
__device__ float g_Q[NELEM];
__device__ float g_K[NELEM];
__device__ float g_V[NELEM];
__device__ __nv_bfloat16 g_attn[NELEM];    // attention output (bf16)
__device__ float g_o[NELEM];               // attn @ Wo (fp32)

// ---------------- weight conversion ----------------
__global__ void cvt_kernel(const float* __restrict__ w, __nv_bfloat16* __restrict__ o, int n) {
    int i = blockIdx.x * blockDim.x + threadIdx.x;
    if (i < n) o[i] = __float2bfloat16(w[i]);
}

// ---------------- LayerNorm 1: tokens -> bf16 x ----------------
__global__ void ln1_kernel(const float* __restrict__ tokens,
                           const float* __restrict__ g, const float* __restrict__ beta,
                           __nv_bfloat16* __restrict__ out) {
    int row = blockIdx.x;
    int tid = threadIdx.x;
    const float* r = tokens + (size_t)row * D_;
    float v[4], s = 0.f, ss = 0.f;
#pragma unroll
    for (int c = 0; c < 4; c++) {
        v[c] = r[tid + 256 * c];
        s += v[c]; ss += v[c] * v[c];
    }
    __shared__ float rs[256], rss[256];
    rs[tid] = s; rss[tid] = ss;
    __syncthreads();
    for (int o = 128; o > 0; o >>= 1) {
        if (tid < o) { rs[tid] += rs[tid + o]; rss[tid] += rss[tid + o]; }
        __syncthreads();
    }
    float mean = rs[0] * (1.0f / D_);
    float var  = rss[0] * (1.0f / D_) - mean * mean;
    float inv  = rsqrtf(var + EPS);
#pragma unroll
    for (int c = 0; c < 4; c++) {
        int idx = tid + 256 * c;
        out[(size_t)row * D_ + idx] =
            __float2bfloat16((v[c] - mean) * inv * g[idx] + beta[idx]);
    }
}

// ---------------- LayerNorm 2: tokens + 0.1*o -> fp32 out ----------------
__global__ void ln2_kernel(const float* __restrict__ tokens,
                           const float* __restrict__ oin,
                           const float* __restrict__ g, const float* __restrict__ beta,
                           float* __restrict__ out) {
    int row = blockIdx.x;
    int tid = threadIdx.x;
    const float* r  = tokens + (size_t)row * D_;
    const float* ro = oin    + (size_t)row * D_;
    float v[4], s = 0.f, ss = 0.f;
#pragma unroll
    for (int c = 0; c < 4; c++) {
        int idx = tid + 256 * c;
        v[c] = r[idx] + 0.1f * ro[idx];
        s += v[c]; ss += v[c] * v[c];
    }
    __shared__ float rs[256], rss[256];
    rs[tid] = s; rss[tid] = ss;
    __syncthreads();
    for (int o = 128; o > 0; o >>= 1) {
        if (tid < o) { rs[tid] += rs[tid + o]; rss[tid] += rss[tid + o]; }
        __syncthreads();
    }
    float mean = rs[0] * (1.0f / D_);
    float var  = rss[0] * (1.0f / D_) - mean * mean;
    float inv  = rsqrtf(var + EPS);
#pragma unroll
    for (int c = 0; c < 4; c++) {
        int idx = tid + 256 * c;
        out[(size_t)row * D_ + idx] = (v[c] - mean) * inv * g[idx] + beta[idx];
    }
}

// ---------------- wmma bf16 GEMM: C[M,1024] = A[M,1024] * B[1024,1024] -----
// blockIdx.z selects (B,C) pair (used for fused QKV; z=0 only for O proj).
constexpr int BM = 128, BN = 128, BK = 32;
constexpr int APAD_LD = 48;   // A smem leading dim (elems)
constexpr int BPAD_LD = 136;  // B smem leading dim (elems)

__global__ void gemm_kernel(const __nv_bfloat16* __restrict__ A,
                            const __nv_bfloat16* __restrict__ B0,
                            const __nv_bfloat16* __restrict__ B1,
                            const __nv_bfloat16* __restrict__ B2,
                            float* __restrict__ C0,
                            float* __restrict__ C1,
                            float* __restrict__ C2) {
    const __nv_bfloat16* Bm = (blockIdx.z == 0) ? B0 : (blockIdx.z == 1) ? B1 : B2;
    float* C = (blockIdx.z == 0) ? C0 : (blockIdx.z == 1) ? C1 : C2;

    __shared__ __align__(16) __nv_bfloat16 As[BM][APAD_LD];
    __shared__ __align__(16) __nv_bfloat16 Bs[BK][BPAD_LD];

    int m0 = blockIdx.y * BM;
    int n0 = blockIdx.x * BN;
    int tid = threadIdx.x;
    int wid = tid >> 5;
    int wm = wid & 3;          // 0..3 -> 32 rows each
    int wn = wid >> 2;         // 0..1 -> 64 cols each

    wmma::fragment<wmma::accumulator, 16, 16, 16, float> cf[2][4];
#pragma unroll
    for (int r = 0; r < 2; r++)
#pragma unroll
        for (int c = 0; c < 4; c++)
            wmma::fill_fragment(cf[r][c], 0.0f);

    for (int k0 = 0; k0 < 1024; k0 += BK) {
        // load A tile 128x32 (512 uint4)
#pragma unroll
        for (int r = 0; r < 2; r++) {
            int idx = tid + r * 256;
            int row = idx >> 2, c4 = idx & 3;
            *(uint4*)&As[row][c4 * 8] =
                *(const uint4*)&A[(size_t)(m0 + row) * 1024 + k0 + c4 * 8];
        }
        // load B tile 32x128 (512 uint4)
#pragma unroll
        for (int r = 0; r < 2; r++) {
            int idx = tid + r * 256;
            int row = idx >> 4, c4 = idx & 15;
            *(uint4*)&Bs[row][c4 * 8] =
                *(const uint4*)&Bm[(size_t)(k0 + row) * 1024 + n0 + c4 * 8];
        }
        __syncthreads();
#pragma unroll
        for (int kk = 0; kk < 2; kk++) {
            wmma::fragment<wmma::matrix_a, 16, 16, 16, __nv_bfloat16, wmma::row_major> af[2];
            wmma::fragment<wmma::matrix_b, 16, 16, 16, __nv_bfloat16, wmma::row_major> bf[4];
#pragma unroll
            for (int r = 0; r < 2; r++)
                wmma::load_matrix_sync(af[r], &As[wm * 32 + r * 16][kk * 16], APAD_LD);
#pragma unroll
            for (int c = 0; c < 4; c++)
                wmma::load_matrix_sync(bf[c], &Bs[kk * 16][wn * 64 + c * 16], BPAD_LD);
#pragma unroll
            for (int r = 0; r < 2; r++)
#pragma unroll
                for (int c = 0; c < 4; c++)
                    wmma::mma_sync(cf[r][c], af[r], bf[c], cf[r][c]);
        }
        __syncthreads();
    }
#pragma unroll
    for (int r = 0; r < 2; r++)
#pragma unroll
        for (int c = 0; c < 4; c++) {
            float* p = C + (size_t)(m0 + wm * 32 + r * 16) * 1024 + n0 + wn * 64 + c * 16;
            wmma::store_matrix_sync(p, cf[r][c], 1024, wmma::mem_row_major);
        }
}

// ---------------- sparse attention ----------------
// One block per (batch, 16-query tile). Union key list in smem; warp-per-key
// scores; per-query softmax; register-accumulated AV with warp-owned d-chunks.
constexpr int QT = 16;
constexpr int MAXU = 800;
constexpr size_t ATTN_SMEM =
    (size_t)QT * H_ * 4          // Qs
  + (size_t)QT * MAXU * 4        // scores
  + (size_t)MAXU * 4             // klist
  + 16;                          // counter

__global__ void attn_kernel(const float* __restrict__ Q,
                            const float* __restrict__ K,
                            const float* __restrict__ V,
                            __nv_bfloat16* __restrict__ attn) {
    extern __shared__ float sm[];
    float* Qs   = sm;                          // [QT][H_]
    float* sc   = Qs + QT * H_;                // [QT][MAXU]
    int*   klist = (int*)(sc + QT * MAXU);     // [MAXU]
    int*   cntp  = klist + MAXU;

    int b  = blockIdx.y;
    int i0 = blockIdx.x * QT;
    int tid = threadIdx.x;
    int lane = tid & 31;
    int wid  = tid >> 5;

    // load Q tile
    const float* Qbase = Q + ((size_t)b * S_ + i0) * H_;
    for (int idx = tid; idx < QT * H_; idx += 256) Qs[idx] = Qbase[idx];
    for (int idx = tid; idx < QT * MAXU; idx += 256) sc[idx] = -INFINITY;
    if (tid == 0) *cntp = 0;
    __syncthreads();

    // build union key list: window-union + global + strided residues of tile
    int imax   = i0 + QT - 1;
    int wstart = max(0, i0 - (WIN - 1));
    for (int j = tid; j <= imax; j += 256) {
        bool inc;
        if (j >= wstart)       inc = true;
        else if (j < GLOB)     inc = true;
        else {
            int u = ((j - i0) % STRIDE_ + STRIDE_) % STRIDE_;
            inc = (u < QT);
        }
        if (inc) { int p = atomicAdd(cntp, 1); klist[p] = j; }
    }
    __syncthreads();
    int cnt = *cntp;

    // scores: warp per key
    for (int ku = wid; ku < cnt; ku += 8) {
        int j = klist[ku];
        const float* Krow = K + ((size_t)b * S_ + j) * H_;
        float kr[32];
#pragma unroll
        for (int t = 0; t < 32; t++) kr[t] = Krow[lane + 32 * t];
#pragma unroll 1
        for (int q = 0; q < QT; q++) {
            int i = i0 + q;
            int dij = i - j;
            bool ok = (dij >= 0) && ((dij < WIN) || ((dij % STRIDE_) == 0) || (j < GLOB));
            if (!ok) continue;
            const float* Qr = Qs + q * H_;
            float p = 0.f;
#pragma unroll
            for (int t = 0; t < 32; t++) p += kr[t] * Qr[lane + 32 * t];
#pragma unroll
            for (int o = 16; o > 0; o >>= 1) p += __shfl_down_sync(0xffffffffu, p, o);
            if (lane == 0) sc[q * MAXU + ku] = p * SCALE;
        }
    }
    __syncthreads();

    // softmax: warp per query
    for (int q = wid; q < QT; q += 8) {
        float m = -INFINITY;
        for (int ku = lane; ku < cnt; ku += 32) m = fmaxf(m, sc[q * MAXU + ku]);
#pragma unroll
        for (int o = 16; o > 0; o >>= 1) m = fmaxf(m, __shfl_xor_sync(0xffffffffu, m, o));
        float s = 0.f;
        for (int ku = lane; ku < cnt; ku += 32) {
            float e = expf(sc[q * MAXU + ku] - m);
            sc[q * MAXU + ku] = e;
            s += e;
        }
#pragma unroll
        for (int o = 16; o > 0; o >>= 1) s += __shfl_xor_sync(0xffffffffu, s, o);
        float inv = 1.f / s;
        for (int ku = lane; ku < cnt; ku += 32) sc[q * MAXU + ku] *= inv;
    }
    __syncthreads();

    // AV: warp owns 128-wide d chunk; accumulate all queries in registers
    int d0 = wid * 128;
    float acc[QT][4];
#pragma unroll
    for (int q = 0; q < QT; q++)
#pragma unroll
        for (int c = 0; c < 4; c++) acc[q][c] = 0.f;

    for (int ku = 0; ku < cnt; ku++) {
        int j = klist[ku];
        const float* Vrow = V + ((size_t)b * S_ + j) * H_ + d0 + lane;
        float v0 = Vrow[0], v1 = Vrow[32], v2 = Vrow[64], v3 = Vrow[96];
#pragma unroll
        for (int q = 0; q < QT; q++) {
            float w = sc[q * MAXU + ku];
            if (w > 0.f) {
                acc[q][0] += w * v0;
                acc[q][1] += w * v1;
                acc[q][2] += w * v2;
                acc[q][3] += w * v3;
            }
        }
    }
#pragma unroll
    for (int q = 0; q < QT; q++) {
        __nv_bfloat16* orow = attn + ((size_t)b * S_ + i0 + q) * H_ + d0 + lane;
        orow[0]  = __float2bfloat16(acc[q][0]);
        orow[32] = __float2bfloat16(acc[q][1]);
        orow[64] = __float2bfloat16(acc[q][2]);
        orow[96] = __float2bfloat16(acc[q][3]);
    }
}

// ---------------- launch ----------------
extern "C" void kernel_launch(void* const* d_in, const int* in_sizes, int n_in,
                              void* d_out, int out_size) {
    const float* tokens = (const float*)d_in[0];
    const float* Wq = (const float*)d_in[1];
    const float* Wk = (const float*)d_in[2];
    const float* Wv = (const float*)d_in[3];
    const float* Wo = (const float*)d_in[4];
    const float* g1 = (const float*)d_in[5];
    const float* b1 = (const float*)d_in[6];
    const float* g2 = (const float*)d_in[7];
    const float* b2 = (const float*)d_in[8];
    float* out = (float*)d_out;

    __nv_bfloat16 *x, *wq, *wk, *wv, *wo, *attn;
    float *Qb, *Kb, *Vb, *ob;
    cudaGetSymbolAddress((void**)&x,    g_x);
    cudaGetSymbolAddress((void**)&wq,   g_wq);
    cudaGetSymbolAddress((void**)&wk,   g_wk);
    cudaGetSymbolAddress((void**)&wv,   g_wv);
    cudaGetSymbolAddress((void**)&wo,   g_wo);
    cudaGetSymbolAddress((void**)&Qb,   g_Q);
    cudaGetSymbolAddress((void**)&Kb,   g_K);
    cudaGetSymbolAddress((void**)&Vb,   g_V);
    cudaGetSymbolAddress((void**)&attn, g_attn);
    cudaGetSymbolAddress((void**)&ob,   g_o);

    int wn = D_ * H_;
    int cvtBlocks = (wn + 255) / 256;
    cvt_kernel<<<cvtBlocks, 256>>>(Wq, wq, wn);
    cvt_kernel<<<cvtBlocks, 256>>>(Wk, wk, wn);
    cvt_kernel<<<cvtBlocks, 256>>>(Wv, wv, wn);
    cvt_kernel<<<cvtBlocks, 256>>>(Wo, wo, wn);

    ln1_kernel<<<ROWS, 256>>>(tokens, g1, b1, x);

    // fused QKV projection
    gemm_kernel<<<dim3(H_ / BN, ROWS / BM, 3), 256>>>(x, wq, wk, wv, Qb, Kb, Vb);

    // sparse attention
    cudaFuncSetAttribute(attn_kernel, cudaFuncAttributeMaxDynamicSharedMemorySize,
                         (int)ATTN_SMEM);
    attn_kernel<<<dim3(S_ / QT, B_), 256, ATTN_SMEM>>>(Qb, Kb, Vb, attn);

    // output projection
    gemm_kernel<<<dim3(D_ / BN, ROWS / BM, 1), 256>>>(attn, wo, wo, wo, ob, ob, ob);

    // residual + LN2
    ln2_kernel<<<ROWS, 256>>>(tokens, ob, g2, b2, out);
}

// round 3
// speedup vs baseline: 1.1903x; 1.1903x over previous
#include <cuda_runtime.h>
#include <cuda_bf16.h>
#include <mma.h>
#include <math.h>

using namespace nvcuda;

// ---------------- problem constants ----------------
constexpr int B_   = 4;
constexpr int S_   = 4096;
constexpr int D_   = 1024;   // token dim
constexpr int H_   = 1024;   // hidden dim
constexpr int WIN  = 256;
constexpr int STRIDE_ = 128;
constexpr int GLOB = 16;
constexpr float EPS = 1e-5f;
constexpr float SCALE = 1.0f / 32.0f;  // 1/sqrt(1024)

constexpr int ROWS = B_ * S_;          // 16384
constexpr size_t NELEM = (size_t)ROWS * D_;  // 16,777,216

// ---------------- scratch (static device globals; allocation-free) ----------
__device__ __nv_bfloat16 g_x[NELEM];       // LN1 output (bf16)
__device__ __nv_bfloat16 g_wq[D_ * H_];
__device__ __nv_bfloat16 g_wk[D_ * H_];
__device__ __nv_bfloat16 g_wv[D_ * D_];
__device__ __nv_bfloat16 g_wo[D_ * D_];
__device__ __nv_bfloat16 g_Q[NELEM];       // bf16 QKV: halves traffic, L2-resident
__device__ __nv_bfloat16 g_K[NELEM];
__device__ __nv_bfloat16 g_V[NELEM];
__device__ __nv_bfloat16 g_attn[NELEM];    // attention output (bf16)
__device__ float g_o[NELEM];               // attn @ Wo (fp32)

// ---------------- cp.async helpers ----------------
__device__ __forceinline__ void cp16(void* sdst, const void* gsrc) {
    unsigned sa = (unsigned)__cvta_generic_to_shared(sdst);
    asm volatile("cp.async.cg.shared.global [%0], [%1], 16;\n" :: "r"(sa), "l"(gsrc));
}
#define CP_COMMIT() asm volatile("cp.async.commit_group;\n" ::: "memory")
#define CP_WAIT1()  asm volatile("cp.async.wait_group 1;\n" ::: "memory")

// ---------------- weight conversion (all 4 weights, 1 launch) --------------
__global__ void cvt4_kernel(const float* __restrict__ w0, const float* __restrict__ w1,
                            const float* __restrict__ w2, const float* __restrict__ w3,
                            __nv_bfloat16* __restrict__ o0, __nv_bfloat16* __restrict__ o1,
                            __nv_bfloat16* __restrict__ o2, __nv_bfloat16* __restrict__ o3) {
    const float* w = (blockIdx.y == 0) ? w0 : (blockIdx.y == 1) ? w1 : (blockIdx.y == 2) ? w2 : w3;
    __nv_bfloat16* o = (blockIdx.y == 0) ? o0 : (blockIdx.y == 1) ? o1 : (blockIdx.y == 2) ? o2 : o3;
    int i = blockIdx.x * blockDim.x + threadIdx.x;
    if (i < D_ * H_) o[i] = __float2bfloat16(w[i]);
}

// ---------------- LayerNorm 1: tokens -> bf16 x ----------------
__global__ void ln1_kernel(const float* __restrict__ tokens,
                           const float* __restrict__ g, const float* __restrict__ beta,
                           __nv_bfloat16* __restrict__ out) {
    int row = blockIdx.x;
    int tid = threadIdx.x;
    const float* r = tokens + (size_t)row * D_;
    float v[4], s = 0.f, ss = 0.f;
#pragma unroll
    for (int c = 0; c < 4; c++) {
        v[c] = r[tid + 256 * c];
        s += v[c]; ss += v[c] * v[c];
    }
    __shared__ float rs[256], rss[256];
    rs[tid] = s; rss[tid] = ss;
    __syncthreads();
    for (int o = 128; o > 0; o >>= 1) {
        if (tid < o) { rs[tid] += rs[tid + o]; rss[tid] += rss[tid + o]; }
        __syncthreads();
    }
    float mean = rs[0] * (1.0f / D_);
    float var  = rss[0] * (1.0f / D_) - mean * mean;
    float inv  = rsqrtf(var + EPS);
#pragma unroll
    for (int c = 0; c < 4; c++) {
        int idx = tid + 256 * c;
        out[(size_t)row * D_ + idx] =
            __float2bfloat16((v[c] - mean) * inv * g[idx] + beta[idx]);
    }
}

// ---------------- LayerNorm 2: tokens + 0.1*o -> fp32 out ----------------
__global__ void ln2_kernel(const float* __restrict__ tokens,
                           const float* __restrict__ oin,
                           const float* __restrict__ g, const float* __restrict__ beta,
                           float* __restrict__ out) {
    int row = blockIdx.x;
    int tid = threadIdx.x;
    const float* r  = tokens + (size_t)row * D_;
    const float* ro = oin    + (size_t)row * D_;
    float v[4], s = 0.f, ss = 0.f;
#pragma unroll
    for (int c = 0; c < 4; c++) {
        int idx = tid + 256 * c;
        v[c] = r[idx] + 0.1f * ro[idx];
        s += v[c]; ss += v[c] * v[c];
    }
    __shared__ float rs[256], rss[256];
    rs[tid] = s; rss[tid] = ss;
    __syncthreads();
    for (int o = 128; o > 0; o >>= 1) {
        if (tid < o) { rs[tid] += rs[tid + o]; rss[tid] += rss[tid + o]; }
        __syncthreads();
    }
    float mean = rs[0] * (1.0f / D_);
    float var  = rss[0] * (1.0f / D_) - mean * mean;
    float inv  = rsqrtf(var + EPS);
#pragma unroll
    for (int c = 0; c < 4; c++) {
        int idx = tid + 256 * c;
        out[(size_t)row * D_ + idx] = (v[c] - mean) * inv * g[idx] + beta[idx];
    }
}

// ---------------- wmma bf16 GEMM with cp.async double buffering -----------
// C[M,1024] = A[M,1024] * B[1024,1024]; blockIdx.z selects (B,C) pair.
constexpr int BM = 128, BN = 128, BK = 32;
constexpr int APAD_LD = 48;   // A smem leading dim (elems)
constexpr int BPAD_LD = 136;  // B smem leading dim (elems)
constexpr int NKT = 1024 / BK;  // 32 k-iterations

template <typename OT>
__global__ void gemm_kernel(const __nv_bfloat16* __restrict__ A,
                            const __nv_bfloat16* __restrict__ B0,
                            const __nv_bfloat16* __restrict__ B1,
                            const __nv_bfloat16* __restrict__ B2,
                            OT* __restrict__ C0,
                            OT* __restrict__ C1,
                            OT* __restrict__ C2) {
    const __nv_bfloat16* Bm = (blockIdx.z == 0) ? B0 : (blockIdx.z == 1) ? B1 : B2;
    OT* C = (blockIdx.z == 0) ? C0 : (blockIdx.z == 1) ? C1 : C2;

    __shared__ __align__(16) __nv_bfloat16 As[2][BM][APAD_LD];
    __shared__ __align__(16) __nv_bfloat16 Bs[2][BK][BPAD_LD];

    int m0 = blockIdx.y * BM;
    int n0 = blockIdx.x * BN;
    int tid = threadIdx.x;
    int lane = tid & 31;
    int wid = tid >> 5;
    int wm = wid & 3;          // 0..3 -> 32 rows each
    int wn = wid >> 2;         // 0..1 -> 64 cols each

    wmma::fragment<wmma::accumulator, 16, 16, 16, float> cf[2][4];
#pragma unroll
    for (int r = 0; r < 2; r++)
#pragma unroll
        for (int c = 0; c < 4; c++)
            wmma::fill_fragment(cf[r][c], 0.0f);

    auto issue = [&](int s, int k0) {
#pragma unroll
        for (int r = 0; r < 2; r++) {
            int idx = tid + r * 256;
            int row = idx >> 2, c4 = idx & 3;
            cp16(&As[s][row][c4 * 8], &A[(size_t)(m0 + row) * 1024 + k0 + c4 * 8]);
        }
#pragma unroll
        for (int r = 0; r < 2; r++) {
            int idx = tid + r * 256;
            int row = idx >> 4, c4 = idx & 15;
            cp16(&Bs[s][row][c4 * 8], &Bm[(size_t)(k0 + row) * 1024 + n0 + c4 * 8]);
        }
    };

    issue(0, 0);
    CP_COMMIT();

    for (int kt = 0; kt < NKT; kt++) {
        if (kt + 1 < NKT) issue((kt + 1) & 1, (kt + 1) * BK);
        CP_COMMIT();           // empty group at tail keeps wait_group 1 correct
        CP_WAIT1();            // all but latest group done -> buf kt&1 ready
        __syncthreads();
        int s = kt & 1;
#pragma unroll
        for (int kk = 0; kk < 2; kk++) {
            wmma::fragment<wmma::matrix_a, 16, 16, 16, __nv_bfloat16, wmma::row_major> af[2];
            wmma::fragment<wmma::matrix_b, 16, 16, 16, __nv_bfloat16, wmma::row_major> bf[4];
#pragma unroll
            for (int r = 0; r < 2; r++)
                wmma::load_matrix_sync(af[r], &As[s][wm * 32 + r * 16][kk * 16], APAD_LD);
#pragma unroll
            for (int c = 0; c < 4; c++)
                wmma::load_matrix_sync(bf[c], &Bs[s][kk * 16][wn * 64 + c * 16], BPAD_LD);
#pragma unroll
            for (int r = 0; r < 2; r++)
#pragma unroll
                for (int c = 0; c < 4; c++)
                    wmma::mma_sync(cf[r][c], af[r], bf[c], cf[r][c]);
        }
        __syncthreads();
    }

    // ---- epilogue ----
    if constexpr (sizeof(OT) == 4) {
        // fp32: direct wmma store
#pragma unroll
        for (int r = 0; r < 2; r++)
#pragma unroll
            for (int c = 0; c < 4; c++) {
                float* p = (float*)C + (size_t)(m0 + wm * 32 + r * 16) * 1024 + n0 + wn * 64 + c * 16;
                wmma::store_matrix_sync(p, cf[r][c], 1024, wmma::mem_row_major);
            }
    } else {
        // bf16: stage per-warp 16x16 tile in smem (overlay on As), convert, store
        __syncthreads();
        float* my = (float*)&As[0][0][0] + wid * 256;
#pragma unroll
        for (int r = 0; r < 2; r++)
#pragma unroll
            for (int c = 0; c < 4; c++) {
                wmma::store_matrix_sync(my, cf[r][c], 16, wmma::mem_row_major);
                __syncwarp();
                int r2 = lane >> 1;
                int cb = (lane & 1) * 8;
                __nv_bfloat16 pk[8];
#pragma unroll
                for (int e = 0; e < 8; e++)
                    pk[e] = __float2bfloat16(my[r2 * 16 + cb + e]);
                __nv_bfloat16* p = (__nv_bfloat16*)C
                    + (size_t)(m0 + wm * 32 + r * 16 + r2) * 1024 + n0 + wn * 64 + c * 16 + cb;
                *(uint4*)p = *(uint4*)pk;
                __syncwarp();
            }
    }
}

// ---------------- sparse attention (bf16 QKV, 512 threads) ----------------
constexpr int QT = 16;
constexpr int MAXU = 800;
constexpr int ATHREADS = 512;   // 16 warps
constexpr size_t ATTN_SMEM =
    (size_t)QT * H_ * 4          // Qs (fp32)
  + (size_t)QT * MAXU * 4        // scores
  + (size_t)MAXU * 4             // klist
  + 16;                          // counter

__global__ void attn_kernel(const __nv_bfloat16* __restrict__ Q,
                            const __nv_bfloat16* __restrict__ K,
                            const __nv_bfloat16* __restrict__ V,
                            __nv_bfloat16* __restrict__ attn) {
    extern __shared__ float sm[];
    float* Qs    = sm;                          // [QT][H_]
    float* sc    = Qs + QT * H_;                // [QT][MAXU]
    int*   klist = (int*)(sc + QT * MAXU);      // [MAXU]
    int*   cntp  = klist + MAXU;

    int b  = blockIdx.y;
    int i0 = blockIdx.x * QT;
    int tid = threadIdx.x;
    int lane = tid & 31;
    int wid  = tid >> 5;

    // load Q tile (bf16 -> fp32 smem)
    const __nv_bfloat16* Qbase = Q + ((size_t)b * S_ + i0) * H_;
    for (int idx = tid; idx < QT * H_; idx += ATHREADS)
        Qs[idx] = __bfloat162float(Qbase[idx]);
    for (int idx = tid; idx < QT * MAXU; idx += ATHREADS) sc[idx] = -INFINITY;
    if (tid == 0) *cntp = 0;
    __syncthreads();

    // build union key list: window-union + global + strided residues of tile
    int imax   = i0 + QT - 1;
    int wstart = max(0, i0 - (WIN - 1));
    for (int j = tid; j <= imax; j += ATHREADS) {
        bool inc;
        if (j >= wstart)       inc = true;
        else if (j < GLOB)     inc = true;
        else {
            int u = ((j - i0) % STRIDE_ + STRIDE_) % STRIDE_;
            inc = (u < QT);
        }
        if (inc) { int p = atomicAdd(cntp, 1); klist[p] = j; }
    }
    __syncthreads();
    int cnt = *cntp;

    // scores: warp per key; bf16x2 K loads, float2 Q smem reads
    for (int ku = wid; ku < cnt; ku += 16) {
        int j = klist[ku];
        const __nv_bfloat162* Krow2 =
            (const __nv_bfloat162*)(K + ((size_t)b * S_ + j) * H_);
        float2 kr[16];
#pragma unroll
        for (int t = 0; t < 16; t++) kr[t] = __bfloat1622float2(Krow2[lane + 32 * t]);
#pragma unroll 1
        for (int q = 0; q < QT; q++) {
            int i = i0 + q;
            int dij = i - j;
            bool ok = (dij >= 0) && ((dij < WIN) || ((dij % STRIDE_) == 0) || (j < GLOB));
            if (!ok) continue;
            const float2* Qr2 = (const float2*)(Qs + (size_t)q * H_);
            float p = 0.f;
#pragma unroll
            for (int t = 0; t < 16; t++) {
                float2 qv = Qr2[lane + 32 * t];
                p += kr[t].x * qv.x + kr[t].y * qv.y;
            }
#pragma unroll
            for (int o = 16; o > 0; o >>= 1) p += __shfl_down_sync(0xffffffffu, p, o);
            if (lane == 0) sc[q * MAXU + ku] = p * SCALE;
        }
    }
    __syncthreads();

    // softmax: warp per query
    if (wid < QT) {
        int q = wid;
        float m = -INFINITY;
        for (int ku = lane; ku < cnt; ku += 32) m = fmaxf(m, sc[q * MAXU + ku]);
#pragma unroll
        for (int o = 16; o > 0; o >>= 1) m = fmaxf(m, __shfl_xor_sync(0xffffffffu, m, o));
        float s = 0.f;
        for (int ku = lane; ku < cnt; ku += 32) {
            float e = expf(sc[q * MAXU + ku] - m);
            sc[q * MAXU + ku] = e;
            s += e;
        }
#pragma unroll
        for (int o = 16; o > 0; o >>= 1) s += __shfl_xor_sync(0xffffffffu, s, o);
        float inv = 1.f / s;
        for (int ku = lane; ku < cnt; ku += 32) sc[q * MAXU + ku] *= inv;
    }
    __syncthreads();

    // AV: warp owns 64-wide d chunk (16 warps x 64 = 1024)
    int d0 = wid * 64;
    float acc[QT][2];
#pragma unroll
    for (int q = 0; q < QT; q++) { acc[q][0] = 0.f; acc[q][1] = 0.f; }

    for (int ku = 0; ku < cnt; ku++) {
        int j = klist[ku];
        const __nv_bfloat162* Vrow2 =
            (const __nv_bfloat162*)(V + ((size_t)b * S_ + j) * H_ + d0);
        float2 v = __bfloat1622float2(Vrow2[lane]);
#pragma unroll
        for (int q = 0; q < QT; q++) {
            float w = sc[q * MAXU + ku];   // uniform across warp -> broadcast
            if (w > 0.f) { acc[q][0] += w * v.x; acc[q][1] += w * v.y; }
        }
    }
#pragma unroll
    for (int q = 0; q < QT; q++) {
        __nv_bfloat162* orow =
            (__nv_bfloat162*)(attn + ((size_t)b * S_ + i0 + q) * H_ + d0);
        orow[lane] = __floats2bfloat162_rn(acc[q][0], acc[q][1]);
    }
}

// ---------------- launch ----------------
extern "C" void kernel_launch(void* const* d_in, const int* in_sizes, int n_in,
                              void* d_out, int out_size) {
    const float* tokens = (const float*)d_in[0];
    const float* Wq = (const float*)d_in[1];
    const float* Wk = (const float*)d_in[2];
    const float* Wv = (const float*)d_in[3];
    const float* Wo = (const float*)d_in[4];
    const float* g1 = (const float*)d_in[5];
    const float* b1 = (const float*)d_in[6];
    const float* g2 = (const float*)d_in[7];
    const float* b2 = (const float*)d_in[8];
    float* out = (float*)d_out;

    __nv_bfloat16 *x, *wq, *wk, *wv, *wo, *Qb, *Kb, *Vb, *attn;
    float *ob;
    cudaGetSymbolAddress((void**)&x,    g_x);
    cudaGetSymbolAddress((void**)&wq,   g_wq);
    cudaGetSymbolAddress((void**)&wk,   g_wk);
    cudaGetSymbolAddress((void**)&wv,   g_wv);
    cudaGetSymbolAddress((void**)&wo,   g_wo);
    cudaGetSymbolAddress((void**)&Qb,   g_Q);
    cudaGetSymbolAddress((void**)&Kb,   g_K);
    cudaGetSymbolAddress((void**)&Vb,   g_V);
    cudaGetSymbolAddress((void**)&attn, g_attn);
    cudaGetSymbolAddress((void**)&ob,   g_o);

    cvt4_kernel<<<dim3((D_ * H_ + 255) / 256, 4), 256>>>(Wq, Wk, Wv, Wo, wq, wk, wv, wo);

    ln1_kernel<<<ROWS, 256>>>(tokens, g1, b1, x);

    // fused QKV projection -> bf16
    gemm_kernel<__nv_bfloat16><<<dim3(H_ / BN, ROWS / BM, 3), 256>>>(
        x, wq, wk, wv, Qb, Kb, Vb);

    // sparse attention
    cudaFuncSetAttribute(attn_kernel, cudaFuncAttributeMaxDynamicSharedMemorySize,
                         (int)ATTN_SMEM);
    attn_kernel<<<dim3(S_ / QT, B_), ATHREADS, ATTN_SMEM>>>(Qb, Kb, Vb, attn);

    // output projection -> fp32
    gemm_kernel<float><<<dim3(D_ / BN, ROWS / BM, 1), 256>>>(
        attn, wo, wo, wo, ob, ob, ob);

    // residual + LN2
    ln2_kernel<<<ROWS, 256>>>(tokens, ob, g2, b2, out);
}

// round 6
// speedup vs baseline: 2.2392x; 1.8811x over previous
#include <cuda_runtime.h>
#include <cuda_bf16.h>
#include <mma.h>
#include <math.h>

using namespace nvcuda;

// ---------------- problem constants ----------------
constexpr int B_   = 4;
constexpr int S_   = 4096;
constexpr int D_   = 1024;   // token dim
constexpr int H_   = 1024;   // hidden dim
constexpr int WIN  = 256;
constexpr int STRIDE_ = 128;
constexpr int GLOB = 16;
constexpr float EPS = 1e-5f;
constexpr float SCALE = 1.0f / 32.0f;  // 1/sqrt(1024)

constexpr int ROWS = B_ * S_;          // 16384
constexpr size_t NELEM = (size_t)ROWS * D_;  // 16,777,216

// ---------------- scratch (static device globals; allocation-free) ----------
__device__ __nv_bfloat16 g_x[NELEM];       // LN1 output (bf16)
__device__ __nv_bfloat16 g_wq[D_ * H_];
__device__ __nv_bfloat16 g_wk[D_ * H_];
__device__ __nv_bfloat16 g_wv[D_ * D_];
__device__ __nv_bfloat16 g_wo[D_ * D_];
__device__ __nv_bfloat16 g_Q[NELEM];
__device__ __nv_bfloat16 g_K[NELEM];
__device__ __nv_bfloat16 g_V[NELEM];
__device__ __nv_bfloat16 g_attn[NELEM];    // attention output (bf16)
__device__ float g_o[NELEM];               // attn @ Wo (fp32)

// ---------------- cp.async helpers ----------------
__device__ __forceinline__ void cp16(void* sdst, const void* gsrc) {
    unsigned sa = (unsigned)__cvta_generic_to_shared(sdst);
    asm volatile("cp.async.cg.shared.global [%0], [%1], 16;\n" :: "r"(sa), "l"(gsrc));
}
#define CP_COMMIT() asm volatile("cp.async.commit_group;\n" ::: "memory")
#define CP_WAIT1()  asm volatile("cp.async.wait_group 1;\n" ::: "memory")

// ---------------- weight conversion (all 4 weights, 1 launch) --------------
__global__ void cvt4_kernel(const float* __restrict__ w0, const float* __restrict__ w1,
                            const float* __restrict__ w2, const float* __restrict__ w3,
                            __nv_bfloat16* __restrict__ o0, __nv_bfloat16* __restrict__ o1,
                            __nv_bfloat16* __restrict__ o2, __nv_bfloat16* __restrict__ o3) {
    const float* w = (blockIdx.y == 0) ? w0 : (blockIdx.y == 1) ? w1 : (blockIdx.y == 2) ? w2 : w3;
    __nv_bfloat16* o = (blockIdx.y == 0) ? o0 : (blockIdx.y == 1) ? o1 : (blockIdx.y == 2) ? o2 : o3;
    int i = blockIdx.x * blockDim.x + threadIdx.x;
    if (i < D_ * H_) o[i] = __float2bfloat16(w[i]);
}

// ---------------- LayerNorm 1: tokens -> bf16 x ----------------
__global__ void ln1_kernel(const float* __restrict__ tokens,
                           const float* __restrict__ g, const float* __restrict__ beta,
                           __nv_bfloat16* __restrict__ out) {
    int row = blockIdx.x;
    int tid = threadIdx.x;
    const float* r = tokens + (size_t)row * D_;
    float v[4], s = 0.f, ss = 0.f;
#pragma unroll
    for (int c = 0; c < 4; c++) {
        v[c] = r[tid + 256 * c];
        s += v[c]; ss += v[c] * v[c];
    }
    __shared__ float rs[256], rss[256];
    rs[tid] = s; rss[tid] = ss;
    __syncthreads();
    for (int o = 128; o > 0; o >>= 1) {
        if (tid < o) { rs[tid] += rs[tid + o]; rss[tid] += rss[tid + o]; }
        __syncthreads();
    }
    float mean = rs[0] * (1.0f / D_);
    float var  = rss[0] * (1.0f / D_) - mean * mean;
    float inv  = rsqrtf(var + EPS);
#pragma unroll
    for (int c = 0; c < 4; c++) {
        int idx = tid + 256 * c;
        out[(size_t)row * D_ + idx] =
            __float2bfloat16((v[c] - mean) * inv * g[idx] + beta[idx]);
    }
}

// ---------------- LayerNorm 2: tokens + 0.1*o -> fp32 out ----------------
__global__ void ln2_kernel(const float* __restrict__ tokens,
                           const float* __restrict__ oin,
                           const float* __restrict__ g, const float* __restrict__ beta,
                           float* __restrict__ out) {
    int row = blockIdx.x;
    int tid = threadIdx.x;
    const float* r  = tokens + (size_t)row * D_;
    const float* ro = oin    + (size_t)row * D_;
    float v[4], s = 0.f, ss = 0.f;
#pragma unroll
    for (int c = 0; c < 4; c++) {
        int idx = tid + 256 * c;
        v[c] = r[idx] + 0.1f * ro[idx];
        s += v[c]; ss += v[c] * v[c];
    }
    __shared__ float rs[256], rss[256];
    rs[tid] = s; rss[tid] = ss;
    __syncthreads();
    for (int o = 128; o > 0; o >>= 1) {
        if (tid < o) { rs[tid] += rs[tid + o]; rss[tid] += rss[tid + o]; }
        __syncthreads();
    }
    float mean = rs[0] * (1.0f / D_);
    float var  = rss[0] * (1.0f / D_) - mean * mean;
    float inv  = rsqrtf(var + EPS);
#pragma unroll
    for (int c = 0; c < 4; c++) {
        int idx = tid + 256 * c;
        out[(size_t)row * D_ + idx] = (v[c] - mean) * inv * g[idx] + beta[idx];
    }
}

// ---------------- wmma bf16 GEMM with cp.async double buffering -----------
constexpr int BM = 128, BN = 128, BK = 32;
constexpr int APAD_LD = 48;
constexpr int BPAD_LD = 136;
constexpr int NKT = 1024 / BK;

template <typename OT>
__global__ void gemm_kernel(const __nv_bfloat16* __restrict__ A,
                            const __nv_bfloat16* __restrict__ B0,
                            const __nv_bfloat16* __restrict__ B1,
                            const __nv_bfloat16* __restrict__ B2,
                            OT* __restrict__ C0,
                            OT* __restrict__ C1,
                            OT* __restrict__ C2) {
    const __nv_bfloat16* Bm = (blockIdx.z == 0) ? B0 : (blockIdx.z == 1) ? B1 : B2;
    OT* C = (blockIdx.z == 0) ? C0 : (blockIdx.z == 1) ? C1 : C2;

    __shared__ __align__(16) __nv_bfloat16 As[2][BM][APAD_LD];
    __shared__ __align__(16) __nv_bfloat16 Bs[2][BK][BPAD_LD];

    int m0 = blockIdx.y * BM;
    int n0 = blockIdx.x * BN;
    int tid = threadIdx.x;
    int lane = tid & 31;
    int wid = tid >> 5;
    int wm = wid & 3;
    int wn = wid >> 2;

    wmma::fragment<wmma::accumulator, 16, 16, 16, float> cf[2][4];
#pragma unroll
    for (int r = 0; r < 2; r++)
#pragma unroll
        for (int c = 0; c < 4; c++)
            wmma::fill_fragment(cf[r][c], 0.0f);

    auto issue = [&](int s, int k0) {
#pragma unroll
        for (int r = 0; r < 2; r++) {
            int idx = tid + r * 256;
            int row = idx >> 2, c4 = idx & 3;
            cp16(&As[s][row][c4 * 8], &A[(size_t)(m0 + row) * 1024 + k0 + c4 * 8]);
        }
#pragma unroll
        for (int r = 0; r < 2; r++) {
            int idx = tid + r * 256;
            int row = idx >> 4, c4 = idx & 15;
            cp16(&Bs[s][row][c4 * 8], &Bm[(size_t)(k0 + row) * 1024 + n0 + c4 * 8]);
        }
    };

    issue(0, 0);
    CP_COMMIT();

    for (int kt = 0; kt < NKT; kt++) {
        if (kt + 1 < NKT) issue((kt + 1) & 1, (kt + 1) * BK);
        CP_COMMIT();
        CP_WAIT1();
        __syncthreads();
        int s = kt & 1;
#pragma unroll
        for (int kk = 0; kk < 2; kk++) {
            wmma::fragment<wmma::matrix_a, 16, 16, 16, __nv_bfloat16, wmma::row_major> af[2];
            wmma::fragment<wmma::matrix_b, 16, 16, 16, __nv_bfloat16, wmma::row_major> bf[4];
#pragma unroll
            for (int r = 0; r < 2; r++)
                wmma::load_matrix_sync(af[r], &As[s][wm * 32 + r * 16][kk * 16], APAD_LD);
#pragma unroll
            for (int c = 0; c < 4; c++)
                wmma::load_matrix_sync(bf[c], &Bs[s][kk * 16][wn * 64 + c * 16], BPAD_LD);
#pragma unroll
            for (int r = 0; r < 2; r++)
#pragma unroll
                for (int c = 0; c < 4; c++)
                    wmma::mma_sync(cf[r][c], af[r], bf[c], cf[r][c]);
        }
        __syncthreads();
    }

    if constexpr (sizeof(OT) == 4) {
#pragma unroll
        for (int r = 0; r < 2; r++)
#pragma unroll
            for (int c = 0; c < 4; c++) {
                float* p = (float*)C + (size_t)(m0 + wm * 32 + r * 16) * 1024 + n0 + wn * 64 + c * 16;
                wmma::store_matrix_sync(p, cf[r][c], 1024, wmma::mem_row_major);
            }
    } else {
        __syncthreads();
        float* my = (float*)&As[0][0][0] + wid * 256;
#pragma unroll
        for (int r = 0; r < 2; r++)
#pragma unroll
            for (int c = 0; c < 4; c++) {
                wmma::store_matrix_sync(my, cf[r][c], 16, wmma::mem_row_major);
                __syncwarp();
                int r2 = lane >> 1;
                int cb = (lane & 1) * 8;
                __nv_bfloat16 pk[8];
#pragma unroll
                for (int e = 0; e < 8; e++)
                    pk[e] = __float2bfloat16(my[r2 * 16 + cb + e]);
                __nv_bfloat16* p = (__nv_bfloat16*)C
                    + (size_t)(m0 + wm * 32 + r * 16 + r2) * 1024 + n0 + wn * 64 + c * 16 + cb;
                *(uint4*)p = *(uint4*)pk;
                __syncwarp();
            }
    }
}

// ---------------- sparse attention v2: tensor-core scores + AV -------------
// One block per (batch, 16-query tile), 512 threads (16 warps).
// Scores: S[16, cnt] = Q[16,1024] @ gathered-K^T via wmma, K staged in
// 256-key x 64-k slabs (cp.async double-buffered). Each warp owns a 16-key
// column tile. Mask+softmax in fp32, weights -> bf16. AV: O[16,1024] =
// W @ gathered-V via wmma, V staged 16 keys/chunk, warp owns 64-wide d slice.
constexpr int QT = 16;
constexpr int MAXU = 800;          // max union keys (<=767 computed)
constexpr int ATHREADS = 512;
constexpr int LDQ  = 1032;         // Q smem ld (bf16)
constexpr int LDK  = 72;           // K slab ld (bf16)
constexpr int LDSC = 800;          // score ld (fp32)
constexpr int LDW  = 808;          // weight ld (bf16)
constexpr int LDV  = 1032;         // V tile ld (bf16)
constexpr int KT_ELEMS = 2 * 256 * LDK;   // 36864 bf16 (also holds V: 2*16*1032=33024)

constexpr size_t ATTN_SMEM =
    (size_t)(QT * LDQ + KT_ELEMS + QT * LDW) * 2   // Qs + Kt/Vt + scb (bf16)
  + (size_t)QT * LDSC * 4                          // sc (fp32)
  + (size_t)MAXU * 4 + 16;                         // klist + cnt

__global__ __launch_bounds__(ATHREADS, 1)
void attn_kernel(const __nv_bfloat16* __restrict__ Q,
                 const __nv_bfloat16* __restrict__ K,
                 const __nv_bfloat16* __restrict__ V,
                 __nv_bfloat16* __restrict__ attn) {
    extern __shared__ char smem_raw[];
    __nv_bfloat16* Qs  = (__nv_bfloat16*)smem_raw;            // [QT][LDQ]
    __nv_bfloat16* Kt  = Qs + QT * LDQ;                       // [2][256][LDK] / V: [2][16][LDV]
    __nv_bfloat16* Vt  = Kt;
    __nv_bfloat16* scb = Kt + KT_ELEMS;                       // [QT][LDW]
    float*         sc  = (float*)(scb + QT * LDW);            // [QT][LDSC]
    int*         klist = (int*)(sc + QT * LDSC);              // [MAXU]
    int*          cntp = klist + MAXU;

    int b    = blockIdx.y;
    int i0   = blockIdx.x * QT;
    int tid  = threadIdx.x;
    int lane = tid & 31;
    int wid  = tid >> 5;

    // ---- stage Q tile (bf16, padded ld) ----
    const __nv_bfloat16* Qbase = Q + ((size_t)b * S_ + i0) * H_;
#pragma unroll
    for (int it = 0; it < 4; it++) {
        int id = tid + it * ATHREADS;     // 0..2047
        int row = id >> 7, seg = id & 127;
        *(uint4*)&Qs[row * LDQ + seg * 8] = *(const uint4*)&Qbase[row * 1024 + seg * 8];
    }

    // ---- deterministic key list (warp 0 ballot scan, ascending) ----
    int imax   = i0 + QT - 1;
    int wstart = max(0, i0 - (WIN - 1));
    if (wid == 0) {
        int c = 0;
        for (int j0 = 0; j0 <= imax; j0 += 32) {
            int j = j0 + lane;
            int u = ((j - i0) % STRIDE_ + STRIDE_) % STRIDE_;
            bool inc = (j <= imax) && ((j >= wstart) || (j < GLOB) || (u < QT));
            unsigned msk = __ballot_sync(0xffffffffu, inc);
            if (inc) klist[c + __popc(msk & ((1u << lane) - 1u))] = j;
            c += __popc(msk);
        }
        if (lane == 0) *cntp = c;
        for (int k = c + lane; k < MAXU; k += 32) klist[k] = 0;  // pad
    }
    __syncthreads();
    int cnt = *cntp;

    // ---- score phase: passes of 256 keys, 16 k-slabs of 64 each ----
    auto stageK = [&](int kb, int s, int buf) {
        int k0 = s * 64;
#pragma unroll
        for (int it = 0; it < 4; it++) {
            int id = tid + it * ATHREADS;   // 0..2047
            int row = id >> 3, seg = id & 7;
            int j = klist[kb + row];
            cp16(&Kt[(size_t)buf * 256 * LDK + row * LDK + seg * 8],
                 K + ((size_t)b * S_ + j) * 1024 + k0 + seg * 8);
        }
    };

    int npass = (cnt + 255) >> 8;
    wmma::fragment<wmma::accumulator, 16, 16, 16, float> sf;
    for (int p = 0; p < npass; p++) {
        int kb = p << 8;
        wmma::fill_fragment(sf, 0.0f);
        stageK(kb, 0, 0);
        CP_COMMIT();
        for (int s = 0; s < 16; s++) {
            if (s < 15) stageK(kb, s + 1, (s + 1) & 1);
            CP_COMMIT();
            CP_WAIT1();
            __syncthreads();
            int buf = s & 1;
            int k0 = s * 64;
#pragma unroll
            for (int i = 0; i < 4; i++) {
                wmma::fragment<wmma::matrix_a, 16, 16, 16, __nv_bfloat16, wmma::row_major> af;
                wmma::fragment<wmma::matrix_b, 16, 16, 16, __nv_bfloat16, wmma::col_major> bf;
                wmma::load_matrix_sync(af, Qs + k0 + i * 16, LDQ);
                wmma::load_matrix_sync(bf, Kt + (size_t)buf * 256 * LDK + wid * 16 * LDK + i * 16, LDK);
                wmma::mma_sync(sf, af, bf, sf);
            }
            __syncthreads();
        }
        wmma::store_matrix_sync(sc + kb + wid * 16, sf, LDSC, wmma::mem_row_major);
    }
    __syncthreads();

    // ---- mask + softmax (warp per query), weights -> bf16 scb ----
    int cnt16 = (cnt + 15) & ~15;
    {
        int q = wid;                 // 16 warps == QT queries
        int i = i0 + q;
        float m = -INFINITY;
        for (int ku = lane; ku < cnt; ku += 32) {
            int j = klist[ku];
            int d = i - j;
            bool ok = (d >= 0) && ((d < WIN) || ((d & (STRIDE_ - 1)) == 0) || (j < GLOB));
            float v = ok ? sc[q * LDSC + ku] * SCALE : -INFINITY;
            sc[q * LDSC + ku] = v;
            m = fmaxf(m, v);
        }
#pragma unroll
        for (int o = 16; o > 0; o >>= 1) m = fmaxf(m, __shfl_xor_sync(0xffffffffu, m, o));
        float ssum = 0.f;
        for (int ku = lane; ku < cnt; ku += 32) {
            float e = __expf(sc[q * LDSC + ku] - m);
            sc[q * LDSC + ku] = e;
            ssum += e;
        }
#pragma unroll
        for (int o = 16; o > 0; o >>= 1) ssum += __shfl_xor_sync(0xffffffffu, ssum, o);
        float inv = 1.f / ssum;
        for (int ku = lane; ku < cnt16; ku += 32) {
            float w = (ku < cnt) ? sc[q * LDSC + ku] * inv : 0.f;
            scb[q * LDW + ku] = __float2bfloat16(w);
        }
    }
    __syncthreads();

    // ---- AV phase: chunks of 16 keys, warp owns 64-wide d slice ----
    auto stageV = [&](int c, int buf) {
#pragma unroll
        for (int it = 0; it < 4; it++) {
            int id = tid + it * ATHREADS;   // 0..2047
            int row = id >> 7, seg = id & 127;
            int j = klist[c * 16 + row];
            cp16(&Vt[(size_t)buf * 16 * LDV + row * LDV + seg * 8],
                 V + ((size_t)b * S_ + j) * 1024 + seg * 8);
        }
    };

    int d0 = wid * 64;
    wmma::fragment<wmma::accumulator, 16, 16, 16, float> of[4];
#pragma unroll
    for (int i = 0; i < 4; i++) wmma::fill_fragment(of[i], 0.0f);

    int nchunk = cnt16 >> 4;
    stageV(0, 0);
    CP_COMMIT();
    for (int c = 0; c < nchunk; c++) {
        if (c + 1 < nchunk) stageV(c + 1, (c + 1) & 1);
        CP_COMMIT();
        CP_WAIT1();
        __syncthreads();
        int buf = c & 1;
        wmma::fragment<wmma::matrix_a, 16, 16, 16, __nv_bfloat16, wmma::row_major> af;
        wmma::load_matrix_sync(af, scb + c * 16, LDW);
#pragma unroll
        for (int i = 0; i < 4; i++) {
            wmma::fragment<wmma::matrix_b, 16, 16, 16, __nv_bfloat16, wmma::row_major> bf;
            wmma::load_matrix_sync(bf, Vt + (size_t)buf * 16 * LDV + d0 + i * 16, LDV);
            wmma::mma_sync(of[i], af, bf, of[i]);
        }
        __syncthreads();
    }

    // ---- epilogue: accum frags -> bf16 gmem (stage through sc region) ----
    float* my = sc + wid * 256;   // 16x16 per warp
#pragma unroll
    for (int i = 0; i < 4; i++) {
        wmma::store_matrix_sync(my, of[i], 16, wmma::mem_row_major);
        __syncwarp();
        int r2 = lane >> 1, cb = (lane & 1) * 8;
        __nv_bfloat16 pk[8];
#pragma unroll
        for (int e = 0; e < 8; e++) pk[e] = __float2bfloat16(my[r2 * 16 + cb + e]);
        *(uint4*)(attn + ((size_t)b * S_ + i0 + r2) * 1024 + d0 + i * 16 + cb) = *(uint4*)pk;
        __syncwarp();
    }
}

// ---------------- launch ----------------
extern "C" void kernel_launch(void* const* d_in, const int* in_sizes, int n_in,
                              void* d_out, int out_size) {
    const float* tokens = (const float*)d_in[0];
    const float* Wq = (const float*)d_in[1];
    const float* Wk = (const float*)d_in[2];
    const float* Wv = (const float*)d_in[3];
    const float* Wo = (const float*)d_in[4];
    const float* g1 = (const float*)d_in[5];
    const float* b1 = (const float*)d_in[6];
    const float* g2 = (const float*)d_in[7];
    const float* b2 = (const float*)d_in[8];
    float* out = (float*)d_out;

    __nv_bfloat16 *x, *wq, *wk, *wv, *wo, *Qb, *Kb, *Vb, *attn;
    float *ob;
    cudaGetSymbolAddress((void**)&x,    g_x);
    cudaGetSymbolAddress((void**)&wq,   g_wq);
    cudaGetSymbolAddress((void**)&wk,   g_wk);
    cudaGetSymbolAddress((void**)&wv,   g_wv);
    cudaGetSymbolAddress((void**)&wo,   g_wo);
    cudaGetSymbolAddress((void**)&Qb,   g_Q);
    cudaGetSymbolAddress((void**)&Kb,   g_K);
    cudaGetSymbolAddress((void**)&Vb,   g_V);
    cudaGetSymbolAddress((void**)&attn, g_attn);
    cudaGetSymbolAddress((void**)&ob,   g_o);

    cvt4_kernel<<<dim3((D_ * H_ + 255) / 256, 4), 256>>>(Wq, Wk, Wv, Wo, wq, wk, wv, wo);

    ln1_kernel<<<ROWS, 256>>>(tokens, g1, b1, x);

    // fused QKV projection -> bf16
    gemm_kernel<__nv_bfloat16><<<dim3(H_ / BN, ROWS / BM, 3), 256>>>(
        x, wq, wk, wv, Qb, Kb, Vb);

    // sparse attention (tensor-core)
    cudaFuncSetAttribute(attn_kernel, cudaFuncAttributeMaxDynamicSharedMemorySize,
                         (int)ATTN_SMEM);
    attn_kernel<<<dim3(S_ / QT, B_), ATHREADS, ATTN_SMEM>>>(Qb, Kb, Vb, attn);

    // output projection -> fp32
    gemm_kernel<float><<<dim3(D_ / BN, ROWS / BM, 1), 256>>>(
        attn, wo, wo, wo, ob, ob, ob);

    // residual + LN2
    ln2_kernel<<<ROWS, 256>>>(tokens, ob, g2, b2, out);
}

// round 10
// speedup vs baseline: 3.0864x; 1.3783x over previous
#include <cuda_runtime.h>
#include <cuda_bf16.h>
#include <mma.h>
#include <math.h>

using namespace nvcuda;

// ---------------- problem constants ----------------
constexpr int B_   = 4;
constexpr int S_   = 4096;
constexpr int D_   = 1024;   // token dim
constexpr int H_   = 1024;   // hidden dim
constexpr int WIN  = 256;
constexpr int STRIDE_ = 128;
constexpr int GLOB = 16;
constexpr float EPS = 1e-5f;
constexpr float SCALE = 1.0f / 32.0f;  // 1/sqrt(1024)

constexpr int ROWS = B_ * S_;          // 16384
constexpr size_t NELEM = (size_t)ROWS * D_;  // 16,777,216

// ---------------- scratch (static device globals; allocation-free) ----------
__device__ __nv_bfloat16 g_x[NELEM];       // LN1 output (bf16)
__device__ __nv_bfloat16 g_wq[D_ * H_];
__device__ __nv_bfloat16 g_wk[D_ * H_];
__device__ __nv_bfloat16 g_wv[D_ * D_];
__device__ __nv_bfloat16 g_wo[D_ * D_];
__device__ __nv_bfloat16 g_Q[NELEM];
__device__ __nv_bfloat16 g_K[NELEM];
__device__ __nv_bfloat16 g_V[NELEM];
__device__ __nv_bfloat16 g_attn[NELEM];    // attention output (bf16)
__device__ float g_o[NELEM];               // attn @ Wo (fp32)

// ---------------- cp.async helpers ----------------
__device__ __forceinline__ void cp16(void* sdst, const void* gsrc) {
    unsigned sa = (unsigned)__cvta_generic_to_shared(sdst);
    asm volatile("cp.async.cg.shared.global [%0], [%1], 16;\n" :: "r"(sa), "l"(gsrc));
}
#define CP_COMMIT() asm volatile("cp.async.commit_group;\n" ::: "memory")
#define CP_WAIT1()  asm volatile("cp.async.wait_group 1;\n" ::: "memory")

// ---------------- weight conversion (all 4 weights, 1 launch) --------------
__global__ void cvt4_kernel(const float* __restrict__ w0, const float* __restrict__ w1,
                            const float* __restrict__ w2, const float* __restrict__ w3,
                            __nv_bfloat16* __restrict__ o0, __nv_bfloat16* __restrict__ o1,
                            __nv_bfloat16* __restrict__ o2, __nv_bfloat16* __restrict__ o3) {
    const float* w = (blockIdx.y == 0) ? w0 : (blockIdx.y == 1) ? w1 : (blockIdx.y == 2) ? w2 : w3;
    __nv_bfloat16* o = (blockIdx.y == 0) ? o0 : (blockIdx.y == 1) ? o1 : (blockIdx.y == 2) ? o2 : o3;
    int i = blockIdx.x * blockDim.x + threadIdx.x;
    if (i < D_ * H_) o[i] = __float2bfloat16(w[i]);
}

// ---------------- LayerNorm 1: tokens -> bf16 x ----------------
__global__ void ln1_kernel(const float* __restrict__ tokens,
                           const float* __restrict__ g, const float* __restrict__ beta,
                           __nv_bfloat16* __restrict__ out) {
    int row = blockIdx.x;
    int tid = threadIdx.x;
    const float* r = tokens + (size_t)row * D_;
    float v[4], s = 0.f, ss = 0.f;
#pragma unroll
    for (int c = 0; c < 4; c++) {
        v[c] = r[tid + 256 * c];
        s += v[c]; ss += v[c] * v[c];
    }
    __shared__ float rs[256], rss[256];
    rs[tid] = s; rss[tid] = ss;
    __syncthreads();
    for (int o = 128; o > 0; o >>= 1) {
        if (tid < o) { rs[tid] += rs[tid + o]; rss[tid] += rss[tid + o]; }
        __syncthreads();
    }
    float mean = rs[0] * (1.0f / D_);
    float var  = rss[0] * (1.0f / D_) - mean * mean;
    float inv  = rsqrtf(var + EPS);
#pragma unroll
    for (int c = 0; c < 4; c++) {
        int idx = tid + 256 * c;
        out[(size_t)row * D_ + idx] =
            __float2bfloat16((v[c] - mean) * inv * g[idx] + beta[idx]);
    }
}

// ---------------- LayerNorm 2: tokens + 0.1*o -> fp32 out ----------------
__global__ void ln2_kernel(const float* __restrict__ tokens,
                           const float* __restrict__ oin,
                           const float* __restrict__ g, const float* __restrict__ beta,
                           float* __restrict__ out) {
    int row = blockIdx.x;
    int tid = threadIdx.x;
    const float* r  = tokens + (size_t)row * D_;
    const float* ro = oin    + (size_t)row * D_;
    float v[4], s = 0.f, ss = 0.f;
#pragma unroll
    for (int c = 0; c < 4; c++) {
        int idx = tid + 256 * c;
        v[c] = r[idx] + 0.1f * ro[idx];
        s += v[c]; ss += v[c] * v[c];
    }
    __shared__ float rs[256], rss[256];
    rs[tid] = s; rss[tid] = ss;
    __syncthreads();
    for (int o = 128; o > 0; o >>= 1) {
        if (tid < o) { rs[tid] += rs[tid + o]; rss[tid] += rss[tid + o]; }
        __syncthreads();
    }
    float mean = rs[0] * (1.0f / D_);
    float var  = rss[0] * (1.0f / D_) - mean * mean;
    float inv  = rsqrtf(var + EPS);
#pragma unroll
    for (int c = 0; c < 4; c++) {
        int idx = tid + 256 * c;
        out[(size_t)row * D_ + idx] = (v[c] - mean) * inv * g[idx] + beta[idx];
    }
}

// ---------------- wmma bf16 GEMM with cp.async double buffering -----------
constexpr int BM = 128, BN = 128, BK = 32;
constexpr int APAD_LD = 48;
constexpr int BPAD_LD = 136;
constexpr int NKT = 1024 / BK;

template <typename OT>
__global__ void gemm_kernel(const __nv_bfloat16* __restrict__ A,
                            const __nv_bfloat16* __restrict__ B0,
                            const __nv_bfloat16* __restrict__ B1,
                            const __nv_bfloat16* __restrict__ B2,
                            OT* __restrict__ C0,
                            OT* __restrict__ C1,
                            OT* __restrict__ C2) {
    const __nv_bfloat16* Bm = (blockIdx.z == 0) ? B0 : (blockIdx.z == 1) ? B1 : B2;
    OT* C = (blockIdx.z == 0) ? C0 : (blockIdx.z == 1) ? C1 : C2;

    __shared__ __align__(16) __nv_bfloat16 As[2][BM][APAD_LD];
    __shared__ __align__(16) __nv_bfloat16 Bs[2][BK][BPAD_LD];

    int m0 = blockIdx.y * BM;
    int n0 = blockIdx.x * BN;
    int tid = threadIdx.x;
    int lane = tid & 31;
    int wid = tid >> 5;
    int wm = wid & 3;
    int wn = wid >> 2;

    wmma::fragment<wmma::accumulator, 16, 16, 16, float> cf[2][4];
#pragma unroll
    for (int r = 0; r < 2; r++)
#pragma unroll
        for (int c = 0; c < 4; c++)
            wmma::fill_fragment(cf[r][c], 0.0f);

    auto issue = [&](int s, int k0) {
#pragma unroll
        for (int r = 0; r < 2; r++) {
            int idx = tid + r * 256;
            int row = idx >> 2, c4 = idx & 3;
            cp16(&As[s][row][c4 * 8], &A[(size_t)(m0 + row) * 1024 + k0 + c4 * 8]);
        }
#pragma unroll
        for (int r = 0; r < 2; r++) {
            int idx = tid + r * 256;
            int row = idx >> 4, c4 = idx & 15;
            cp16(&Bs[s][row][c4 * 8], &Bm[(size_t)(k0 + row) * 1024 + n0 + c4 * 8]);
        }
    };

    issue(0, 0);
    CP_COMMIT();

    for (int kt = 0; kt < NKT; kt++) {
        if (kt + 1 < NKT) issue((kt + 1) & 1, (kt + 1) * BK);
        CP_COMMIT();
        CP_WAIT1();
        __syncthreads();
        int s = kt & 1;
#pragma unroll
        for (int kk = 0; kk < 2; kk++) {
            wmma::fragment<wmma::matrix_a, 16, 16, 16, __nv_bfloat16, wmma::row_major> af[2];
            wmma::fragment<wmma::matrix_b, 16, 16, 16, __nv_bfloat16, wmma::row_major> bf[4];
#pragma unroll
            for (int r = 0; r < 2; r++)
                wmma::load_matrix_sync(af[r], &As[s][wm * 32 + r * 16][kk * 16], APAD_LD);
#pragma unroll
            for (int c = 0; c < 4; c++)
                wmma::load_matrix_sync(bf[c], &Bs[s][kk * 16][wn * 64 + c * 16], BPAD_LD);
#pragma unroll
            for (int r = 0; r < 2; r++)
#pragma unroll
                for (int c = 0; c < 4; c++)
                    wmma::mma_sync(cf[r][c], af[r], bf[c], cf[r][c]);
        }
        __syncthreads();
    }

    if constexpr (sizeof(OT) == 4) {
#pragma unroll
        for (int r = 0; r < 2; r++)
#pragma unroll
            for (int c = 0; c < 4; c++) {
                float* p = (float*)C + (size_t)(m0 + wm * 32 + r * 16) * 1024 + n0 + wn * 64 + c * 16;
                wmma::store_matrix_sync(p, cf[r][c], 1024, wmma::mem_row_major);
            }
    } else {
        __syncthreads();
        float* my = (float*)&As[0][0][0] + wid * 256;
#pragma unroll
        for (int r = 0; r < 2; r++)
#pragma unroll
            for (int c = 0; c < 4; c++) {
                wmma::store_matrix_sync(my, cf[r][c], 16, wmma::mem_row_major);
                __syncwarp();
                int r2 = lane >> 1;
                int cb = (lane & 1) * 8;
                __nv_bfloat16 pk[8];
#pragma unroll
                for (int e = 0; e < 8; e++)
                    pk[e] = __float2bfloat16(my[r2 * 16 + cb + e]);
                __nv_bfloat16* p = (__nv_bfloat16*)C
                    + (size_t)(m0 + wm * 32 + r * 16 + r2) * 1024 + n0 + wn * 64 + c * 16 + cb;
                *(uint4*)p = *(uint4*)pk;
                __syncwarp();
            }
    }
}

// ---------------- sparse attention v3: warp-autonomous pipelines -----------
// One block per (batch, 16-query tile), 512 threads (16 warps), 3 block
// barriers total. Score phase: warp w owns key-tiles {w, w+16, ...}; private
// 2-deep cp.async pipeline stages its own 16 K-rows x 64-k slabs; 4 wmma per
// slab; no __syncthreads in the loop. AV phase: warp owns a 64-wide d slice,
// private pipeline over 16-key V chunks.
constexpr int QT = 16;
constexpr int MAXU = 800;          // max union keys (<=767 computed)
constexpr int ATHREADS = 512;
constexpr int LDQ  = 1032;         // Q smem ld (bf16)
constexpr int LDK  = 72;           // K/V slab ld (bf16)
constexpr int LDSC = 800;          // score ld (fp32)
constexpr int LDW  = 808;          // weight ld (bf16)
constexpr int WBUF = 16 * LDK;     // one slab buffer (elems)

constexpr size_t ATTN_SMEM =
    (size_t)QT * LDQ * 2               // Qs
  + (size_t)16 * 2 * WBUF * 2          // per-warp K/V double buffers (73728B)
  + (size_t)QT * LDW * 2               // scb (bf16 weights)
  + (size_t)QT * LDSC * 4              // sc (fp32 scores)
  + (size_t)MAXU * 4 + 16;             // klist + cnt

__global__ __launch_bounds__(ATHREADS, 1)
void attn_kernel(const __nv_bfloat16* __restrict__ Q,
                 const __nv_bfloat16* __restrict__ K,
                 const __nv_bfloat16* __restrict__ V,
                 __nv_bfloat16* __restrict__ attn) {
    extern __shared__ char smem_raw[];
    __nv_bfloat16* Qs  = (__nv_bfloat16*)smem_raw;            // [QT][LDQ]
    __nv_bfloat16* Kb  = Qs + QT * LDQ;                       // [16][2][16][LDK]
    __nv_bfloat16* scb = Kb + 16 * 2 * WBUF;                  // [QT][LDW]
    float*         sc  = (float*)(scb + QT * LDW);            // [QT][LDSC]
    int*         klist = (int*)(sc + QT * LDSC);              // [MAXU]
    int*          cntp = klist + MAXU;

    int b    = blockIdx.y;
    int i0   = (gridDim.x - 1 - blockIdx.x) * QT;   // heaviest tiles first
    int tid  = threadIdx.x;
    int lane = tid & 31;
    int wid  = tid >> 5;

    // ---- stage Q tile (bf16, padded ld) ----
    const __nv_bfloat16* Qbase = Q + ((size_t)b * S_ + i0) * H_;
#pragma unroll
    for (int it = 0; it < 4; it++) {
        int id = tid + it * ATHREADS;     // 0..2047
        int row = id >> 7, seg = id & 127;
        *(uint4*)&Qs[row * LDQ + seg * 8] = *(const uint4*)&Qbase[row * 1024 + seg * 8];
    }

    // ---- deterministic key list (warp 0 ballot scan, ascending) ----
    int imax   = i0 + QT - 1;
    int wstart = max(0, i0 - (WIN - 1));
    if (wid == 0) {
        int c = 0;
        for (int j0 = 0; j0 <= imax; j0 += 32) {
            int j = j0 + lane;
            int u = ((j - i0) % STRIDE_ + STRIDE_) % STRIDE_;
            bool inc = (j <= imax) && ((j >= wstart) || (j < GLOB) || (u < QT));
            unsigned msk = __ballot_sync(0xffffffffu, inc);
            if (inc) klist[c + __popc(msk & ((1u << lane) - 1u))] = j;
            c += __popc(msk);
        }
        if (lane == 0) *cntp = c;
        for (int k = c + lane; k < MAXU; k += 32) klist[k] = 0;  // pad
    }
    __syncthreads();                                   // barrier #1
    int cnt = *cntp;
    int ntiles = (cnt + 15) >> 4;

    __nv_bfloat16* Kw = Kb + wid * 2 * WBUF;           // this warp's buffers
    const __nv_bfloat16* Kbase = K + (size_t)b * S_ * H_;
    const __nv_bfloat16* Vbase = V + (size_t)b * S_ * H_;

    // ---- score phase: warp-private pipeline over (tile, slab) ----
    {
        int nmy = 0;
        for (int kt = wid; kt < ntiles; kt += 16) nmy++;
        int tslabs = nmy * 16;

        auto issueK = [&](int it) {
            int buf = it & 1;
            int kt  = wid + ((it >> 4) << 4);
            int k0  = (it & 15) * 64;
#pragma unroll
            for (int l = 0; l < 4; l++) {
                int id = lane + 32 * l;      // 0..127
                int row = id >> 3, seg = id & 7;
                int j = klist[kt * 16 + row];
                cp16(&Kw[buf * WBUF + row * LDK + seg * 8],
                     Kbase + (size_t)j * 1024 + k0 + seg * 8);
            }
        };

        wmma::fragment<wmma::accumulator, 16, 16, 16, float> sf;
        wmma::fill_fragment(sf, 0.0f);
        if (tslabs > 0) { issueK(0); }
        CP_COMMIT();
        for (int it = 0; it < tslabs; it++) {
            if (it + 1 < tslabs) issueK(it + 1);
            CP_COMMIT();
            CP_WAIT1();
            __syncwarp();
            int buf = it & 1;
            int k0  = (it & 15) * 64;
#pragma unroll
            for (int i = 0; i < 4; i++) {
                wmma::fragment<wmma::matrix_a, 16, 16, 16, __nv_bfloat16, wmma::row_major> af;
                wmma::fragment<wmma::matrix_b, 16, 16, 16, __nv_bfloat16, wmma::col_major> bf;
                wmma::load_matrix_sync(af, Qs + k0 + i * 16, LDQ);
                wmma::load_matrix_sync(bf, Kw + buf * WBUF + i * 16, LDK);
                wmma::mma_sync(sf, af, bf, sf);
            }
            if ((it & 15) == 15) {
                int kt = wid + ((it >> 4) << 4);
                wmma::store_matrix_sync(sc + kt * 16, sf, LDSC, wmma::mem_row_major);
                wmma::fill_fragment(sf, 0.0f);
            }
        }
    }
    __syncthreads();                                   // barrier #2

    // ---- mask + softmax (warp per query), weights -> bf16 scb ----
    int cnt16 = ntiles << 4;
    {
        int q = wid;
        int i = i0 + q;
        float m = -INFINITY;
        for (int ku = lane; ku < cnt; ku += 32) {
            int j = klist[ku];
            int d = i - j;
            bool ok = (d >= 0) && ((d < WIN) || ((d & (STRIDE_ - 1)) == 0) || (j < GLOB));
            float v = ok ? sc[q * LDSC + ku] * SCALE : -INFINITY;
            sc[q * LDSC + ku] = v;
            m = fmaxf(m, v);
        }
#pragma unroll
        for (int o = 16; o > 0; o >>= 1) m = fmaxf(m, __shfl_xor_sync(0xffffffffu, m, o));
        float ssum = 0.f;
        for (int ku = lane; ku < cnt; ku += 32) {
            float e = __expf(sc[q * LDSC + ku] - m);
            sc[q * LDSC + ku] = e;
            ssum += e;
        }
#pragma unroll
        for (int o = 16; o > 0; o >>= 1) ssum += __shfl_xor_sync(0xffffffffu, ssum, o);
        float inv = 1.f / ssum;
        for (int ku = lane; ku < cnt16; ku += 32) {
            float w = (ku < cnt) ? sc[q * LDSC + ku] * inv : 0.f;
            scb[q * LDW + ku] = __float2bfloat16(w);
        }
    }
    __syncthreads();                                   // barrier #3

    // ---- AV phase: warp owns 64-wide d slice; private pipeline ------------
    int d0 = wid * 64;
    {
        auto issueV = [&](int c) {
            int buf = c & 1;
#pragma unroll
            for (int l = 0; l < 4; l++) {
                int id = lane + 32 * l;
                int row = id >> 3, seg = id & 7;
                int j = klist[c * 16 + row];
                cp16(&Kw[buf * WBUF + row * LDK + seg * 8],
                     Vbase + (size_t)j * 1024 + d0 + seg * 8);
            }
        };

        wmma::fragment<wmma::accumulator, 16, 16, 16, float> of[4];
#pragma unroll
        for (int i = 0; i < 4; i++) wmma::fill_fragment(of[i], 0.0f);

        issueV(0);
        CP_COMMIT();
        for (int c = 0; c < ntiles; c++) {
            if (c + 1 < ntiles) issueV(c + 1);
            CP_COMMIT();
            CP_WAIT1();
            __syncwarp();
            int buf = c & 1;
            wmma::fragment<wmma::matrix_a, 16, 16, 16, __nv_bfloat16, wmma::row_major> af;
            wmma::load_matrix_sync(af, scb + c * 16, LDW);
#pragma unroll
            for (int i = 0; i < 4; i++) {
                wmma::fragment<wmma::matrix_b, 16, 16, 16, __nv_bfloat16, wmma::row_major> bf;
                wmma::load_matrix_sync(bf, Kw + buf * WBUF + i * 16, LDK);
                wmma::mma_sync(of[i], af, bf, of[i]);
            }
        }

        // ---- epilogue: frags -> bf16 gmem (warp-local staging in sc) ----
        float* my = sc + wid * 256;
#pragma unroll
        for (int i = 0; i < 4; i++) {
            wmma::store_matrix_sync(my, of[i], 16, wmma::mem_row_major);
            __syncwarp();
            int r2 = lane >> 1, cb = (lane & 1) * 8;
            __nv_bfloat16 pk[8];
#pragma unroll
            for (int e = 0; e < 8; e++) pk[e] = __float2bfloat16(my[r2 * 16 + cb + e]);
            *(uint4*)(attn + ((size_t)b * S_ + i0 + r2) * 1024 + d0 + i * 16 + cb) = *(uint4*)pk;
            __syncwarp();
        }
    }
}

// ---------------- launch ----------------
extern "C" void kernel_launch(void* const* d_in, const int* in_sizes, int n_in,
                              void* d_out, int out_size) {
    const float* tokens = (const float*)d_in[0];
    const float* Wq = (const float*)d_in[1];
    const float* Wk = (const float*)d_in[2];
    const float* Wv = (const float*)d_in[3];
    const float* Wo = (const float*)d_in[4];
    const float* g1 = (const float*)d_in[5];
    const float* b1 = (const float*)d_in[6];
    const float* g2 = (const float*)d_in[7];
    const float* b2 = (const float*)d_in[8];
    float* out = (float*)d_out;

    __nv_bfloat16 *x, *wq, *wk, *wv, *wo, *Qb, *Kb, *Vb, *attn;
    float *ob;
    cudaGetSymbolAddress((void**)&x,    g_x);
    cudaGetSymbolAddress((void**)&wq,   g_wq);
    cudaGetSymbolAddress((void**)&wk,   g_wk);
    cudaGetSymbolAddress((void**)&wv,   g_wv);
    cudaGetSymbolAddress((void**)&wo,   g_wo);
    cudaGetSymbolAddress((void**)&Qb,   g_Q);
    cudaGetSymbolAddress((void**)&Kb,   g_K);
    cudaGetSymbolAddress((void**)&Vb,   g_V);
    cudaGetSymbolAddress((void**)&attn, g_attn);
    cudaGetSymbolAddress((void**)&ob,   g_o);

    cvt4_kernel<<<dim3((D_ * H_ + 255) / 256, 4), 256>>>(Wq, Wk, Wv, Wo, wq, wk, wv, wo);

    ln1_kernel<<<ROWS, 256>>>(tokens, g1, b1, x);

    // fused QKV projection -> bf16
    gemm_kernel<__nv_bfloat16><<<dim3(H_ / BN, ROWS / BM, 3), 256>>>(
        x, wq, wk, wv, Qb, Kb, Vb);

    // sparse attention (warp-autonomous tensor-core)
    cudaFuncSetAttribute(attn_kernel, cudaFuncAttributeMaxDynamicSharedMemorySize,
                         (int)ATTN_SMEM);
    attn_kernel<<<dim3(S_ / QT, B_), ATHREADS, ATTN_SMEM>>>(Qb, Kb, Vb, attn);

    // output projection -> fp32
    gemm_kernel<float><<<dim3(D_ / BN, ROWS / BM, 1), 256>>>(
        attn, wo, wo, wo, ob, ob, ob);

    // residual + LN2
    ln2_kernel<<<ROWS, 256>>>(tokens, ob, g2, b2, out);
}